// round 14
// baseline (speedup 1.0000x reference)
#include <cuda_runtime.h>

#define BDIM 128
#define HDIM 32
#define SDIM 64
#define DDIM 128
#define STARTLEN 32
#define NT 512                        // 16 warps, G=4 batches per CTA
#define G 4
#define BSTR (HDIM * SDIM * DDIM)

// SMEM (floats), total 26368 fl = 105472 B -> 2 CTAs/SM
// Vs[2][64][128] (batches 0,1 only), curT[128][4], red[18 slots][4][128], att[4][64]
#define VS   0
#define CURT 16384
#define RED  16896
#define ATT  26112
#define SMEM_FLOATS 26368

// Fused weights per head: [h][384][128]  (Wo@Wq | Wo@Wk | Wo@Wv)
__device__ float g_comb[HDIM * 3 * DDIM * DDIM];

// ---------------- fuse kernel: C = Wo @ Wm (unchanged) ----------------
__global__ void __launch_bounds__(256)
fuse_weights_kernel(const float* __restrict__ wq, const float* __restrict__ wk,
                    const float* __restrict__ wv, const float* __restrict__ wo)
{
    __shared__ float Ws[DDIM * DDIM];
    __shared__ float Wop[32 * DDIM];
    const int h    = blockIdx.x / 12;
    const int rem  = blockIdx.x % 12;
    const int m    = rem >> 2;
    const int d0   = (rem & 3) << 5;
    const int t    = threadIdx.x;

    const float* Wm = ((m == 0) ? wq : ((m == 1) ? wk : wv)) + (size_t)h * DDIM * DDIM;
    const float* Wo = wo + (size_t)h * DDIM * DDIM;

    for (int i = t; i < DDIM * DDIM / 4; i += 256)
        ((float4*)Ws)[i] = ((const float4*)Wm)[i];
    for (int i = t; i < 32 * DDIM / 4; i += 256)
        ((float4*)Wop)[i] = ((const float4*)(Wo + d0 * DDIM))[i];
    __syncthreads();

    const int c = t & 15;
    const int r = t >> 4;
    float acc[2][8];
    #pragma unroll
    for (int i = 0; i < 2; ++i)
        #pragma unroll
        for (int j = 0; j < 8; ++j) acc[i][j] = 0.f;

    #pragma unroll 4
    for (int e = 0; e < DDIM; ++e) {
        float4 wm0 = *(const float4*)&Ws[e * DDIM + c * 8];
        float4 wm1 = *(const float4*)&Ws[e * DDIM + c * 8 + 4];
        #pragma unroll
        for (int i = 0; i < 2; ++i) {
            float wo_v = Wop[(r * 2 + i) * DDIM + e];
            acc[i][0] += wo_v * wm0.x; acc[i][1] += wo_v * wm0.y;
            acc[i][2] += wo_v * wm0.z; acc[i][3] += wo_v * wm0.w;
            acc[i][4] += wo_v * wm1.x; acc[i][5] += wo_v * wm1.y;
            acc[i][6] += wo_v * wm1.z; acc[i][7] += wo_v * wm1.w;
        }
    }

    float* dst = g_comb + ((size_t)h * 384 + m * DDIM + d0) * DDIM;
    #pragma unroll
    for (int i = 0; i < 2; ++i) {
        *(float4*)&dst[(r * 2 + i) * DDIM + c * 8]     = make_float4(acc[i][0], acc[i][1], acc[i][2], acc[i][3]);
        *(float4*)&dst[(r * 2 + i) * DDIM + c * 8 + 4] = make_float4(acc[i][4], acc[i][5], acc[i][6], acc[i][7]);
    }
}

// ---------------- decode kernel ----------------
__global__ void __launch_bounds__(NT, 2)
attn_decode_kernel(const float* __restrict__ x_in,
                   const float* __restrict__ k_in,
                   const float* __restrict__ v_in,
                   const float* __restrict__ wq,
                   const float* __restrict__ wk,
                   const float* __restrict__ wv,
                   const float* __restrict__ wo,
                   float* k_out, float* v_out, float* __restrict__ x_out)
{
    extern __shared__ float sm[];

    const int t = threadIdx.x;
    const int w = t >> 5;
    const int l = t & 31;
    const int h  = blockIdx.x >> 5;          // 32 batch-groups per head
    const int b0 = (blockIdx.x & 31) << 2;   // 4 batches per CTA

    float* kg = k_out + (size_t)(b0 * HDIM + h) * (SDIM * DDIM);
    float* vg = v_out + (size_t)(b0 * HDIM + h) * (SDIM * DDIM);

    // ---- prologue: K -> k_out (global), V -> v_out (+ Vs smem for b<2), x -> curT ----
    #pragma unroll
    for (int b = 0; b < G; ++b) {
        const float4* kin = (const float4*)(k_in + (size_t)((b0 + b) * HDIM + h) * (SDIM * DDIM));
        const float4* vin = (const float4*)(v_in + (size_t)((b0 + b) * HDIM + h) * (SDIM * DDIM));
        float4* kd = (float4*)(kg + (size_t)b * BSTR);
        float4* vd = (float4*)(vg + (size_t)b * BSTR);
        for (int i = t; i < SDIM * DDIM / 4; i += NT) {
            kd[i] = kin[i];
            float4 vv = vin[i];
            vd[i] = vv;
            if (b < 2) *(float4*)&sm[VS + b * 8192 + 4 * i] = vv;
        }
    }
    {
        const int b = t >> 7, d = t & 127;
        sm[CURT + d * 4 + b] = x_in[(size_t)((b0 + b) * HDIM + h) * DDIM + d];
    }
    __syncthreads();

    // P1 split: 384 rows, warp w -> rows [24w, 24w+24); straddles at w5 (q|k), w10 (k|v)
    const int r0  = w * 24;
    const int mA  = r0 >> 7;
    const int dA  = r0 & 127;
    const int nA  = min(24, 128 - dA);
    const int nB  = 24 - nA;
    const int extra = (w > 5) + (w > 10);
    const int slotA = w + extra;             // q slots 0-5, k slots 6-11, v slots 12-17
    const int slotB = slotA + 1;

    const float* origM[3] = { wq + (size_t)h * DDIM * DDIM,
                              wk + (size_t)h * DDIM * DDIM,
                              wv + (size_t)h * DDIM * DDIM };
    const float* Ch = g_comb + (size_t)h * 384 * DDIM;

    const float4* origA4  = (const float4*)(origM[mA] + (size_t)dA * DDIM);
    const float4* fusedA4 = (const float4*)(Ch + (size_t)r0 * DDIM);
    const float4* origB4  = (nB > 0) ? (const float4*)origM[mA + 1] : nullptr;
    const float4* fusedB4 = (const float4*)(Ch + (size_t)(r0 + nA) * DDIM);

    const int p2b = w >> 2, p2s0 = (w & 3) << 4;     // P2: (batch, s-quarter)
    const int p4b = t >> 7, p4d = t & 127;           // reduce/P4: (batch, d)

    for (int gen = STARTLEN; gen < SDIM; ++gen) {
        const bool first = (gen == STARTLEN);

        // ===== P1: projections, 4 batches per weight load (curT broadcast LDS.128) =====
        {
            const float4* Wp = first ? origA4 : fusedA4;
            float4 a0 = {0,0,0,0}, a1 = {0,0,0,0}, a2 = {0,0,0,0}, a3 = {0,0,0,0};
            #pragma unroll 8
            for (int i = 0; i < nA; ++i) {
                float4 wv4 = Wp[i * 32 + l];
                float4 x4  = *(const float4*)&sm[CURT + (dA + i) * 4];
                a0.x += x4.x * wv4.x; a0.y += x4.x * wv4.y; a0.z += x4.x * wv4.z; a0.w += x4.x * wv4.w;
                a1.x += x4.y * wv4.x; a1.y += x4.y * wv4.y; a1.z += x4.y * wv4.z; a1.w += x4.y * wv4.w;
                a2.x += x4.z * wv4.x; a2.y += x4.z * wv4.y; a2.z += x4.z * wv4.z; a2.w += x4.z * wv4.w;
                a3.x += x4.w * wv4.x; a3.y += x4.w * wv4.y; a3.z += x4.w * wv4.z; a3.w += x4.w * wv4.w;
            }
            *(float4*)&sm[RED + (slotA * 4 + 0) * DDIM + (l << 2)] = a0;
            *(float4*)&sm[RED + (slotA * 4 + 1) * DDIM + (l << 2)] = a1;
            *(float4*)&sm[RED + (slotA * 4 + 2) * DDIM + (l << 2)] = a2;
            *(float4*)&sm[RED + (slotA * 4 + 3) * DDIM + (l << 2)] = a3;
            if (nB > 0) {
                const float4* Wp2 = first ? origB4 : fusedB4;
                float4 c0 = {0,0,0,0}, c1 = {0,0,0,0}, c2 = {0,0,0,0}, c3 = {0,0,0,0};
                #pragma unroll 8
                for (int i = 0; i < nB; ++i) {
                    float4 wv4 = Wp2[i * 32 + l];
                    float4 x4  = *(const float4*)&sm[CURT + i * 4];
                    c0.x += x4.x * wv4.x; c0.y += x4.x * wv4.y; c0.z += x4.x * wv4.z; c0.w += x4.x * wv4.w;
                    c1.x += x4.y * wv4.x; c1.y += x4.y * wv4.y; c1.z += x4.y * wv4.z; c1.w += x4.y * wv4.w;
                    c2.x += x4.z * wv4.x; c2.y += x4.z * wv4.y; c2.z += x4.z * wv4.z; c2.w += x4.z * wv4.w;
                    c3.x += x4.w * wv4.x; c3.y += x4.w * wv4.y; c3.z += x4.w * wv4.z; c3.w += x4.w * wv4.w;
                }
                *(float4*)&sm[RED + (slotB * 4 + 0) * DDIM + (l << 2)] = c0;
                *(float4*)&sm[RED + (slotB * 4 + 1) * DDIM + (l << 2)] = c1;
                *(float4*)&sm[RED + (slotB * 4 + 2) * DDIM + (l << 2)] = c2;
                *(float4*)&sm[RED + (slotB * 4 + 3) * DDIM + (l << 2)] = c3;
            }
        }
        __syncthreads();

        // ===== reduce: q (slots 0-5) -> RED rows 0-3; k (6-11) -> kg; v (12-17) -> vg (+Vs b<2) =====
        {
            const int b = p4b, e = p4d;
            float qv = 0.f, kv = 0.f, vv = 0.f;
            #pragma unroll
            for (int s = 0; s < 6; ++s)  qv += sm[RED + (s * 4 + b) * DDIM + e];
            #pragma unroll
            for (int s = 6; s < 12; ++s) kv += sm[RED + (s * 4 + b) * DDIM + e];
            #pragma unroll
            for (int s = 12; s < 18; ++s) vv += sm[RED + (s * 4 + b) * DDIM + e];
            sm[RED + b * DDIM + e] = qv * 0.125f;         // final q in slot-0 rows (own cell)
            kg[(size_t)b * BSTR + gen * DDIM + e] = kv;
            vg[(size_t)b * BSTR + gen * DDIM + e] = vv;
            if (b < 2) sm[VS + (b * SDIM + gen) * DDIM + e] = vv;
        }
        __syncthreads();

        // ===== P2: QK scores from global K, 16 warps = (batch, s-quarter) =====
        {
            float4 q4 = *(const float4*)&sm[RED + p2b * DDIM + (l << 2)];
            const float4* kb4 = (const float4*)(kg + (size_t)p2b * BSTR) + l;
            #pragma unroll 16
            for (int r = 0; r < 16; ++r) {
                int s = p2s0 + r;
                float4 k4 = kb4[s * 32];
                float p = k4.x * q4.x + k4.y * q4.y + k4.z * q4.z + k4.w * q4.w;
                #pragma unroll
                for (int o = 16; o > 0; o >>= 1) p += __shfl_xor_sync(0xFFFFFFFFu, p, o);
                if (l == 0) sm[ATT + p2b * SDIM + s] = p;
            }
        }
        __syncthreads();

        // ===== P4: per-warp register softmax + AV (smem V for b<2, global V for b>=2) =====
        {
            const int b = p4b, d = p4d;
            float s0 = sm[ATT + b * SDIM + l];
            float s1 = sm[ATT + b * SDIM + 32 + l];
            float mx = fmaxf(s0, s1);
            #pragma unroll
            for (int o = 16; o > 0; o >>= 1) mx = fmaxf(mx, __shfl_xor_sync(0xFFFFFFFFu, mx, o));
            float e0 = __expf(s0 - mx);
            float e1 = __expf(s1 - mx);
            float su = e0 + e1;
            #pragma unroll
            for (int o = 16; o > 0; o >>= 1) su += __shfl_xor_sync(0xFFFFFFFFu, su, o);
            float inv = 1.0f / su;
            float p0 = e0 * inv, p1 = e1 * inv;

            float acc = 0.f;
            if (b < 2) {                                   // warp-uniform branch
                const float* vb = sm + VS + b * (SDIM * DDIM) + d;
                #pragma unroll 8
                for (int s = 0; s < 32; ++s) {
                    float a = __shfl_sync(0xFFFFFFFFu, p0, s);
                    acc += a * vb[s * DDIM];
                }
                #pragma unroll 8
                for (int s = 0; s < 32; ++s) {
                    float a = __shfl_sync(0xFFFFFFFFu, p1, s);
                    acc += a * vb[(32 + s) * DDIM];
                }
            } else {
                const float* vb = vg + (size_t)b * BSTR + d;
                #pragma unroll 8
                for (int s = 0; s < 32; ++s) {
                    float a = __shfl_sync(0xFFFFFFFFu, p0, s);
                    acc += a * vb[s * DDIM];
                }
                #pragma unroll 8
                for (int s = 0; s < 32; ++s) {
                    float a = __shfl_sync(0xFFFFFFFFu, p1, s);
                    acc += a * vb[(32 + s) * DDIM];
                }
            }
            sm[CURT + d * 4 + b] = acc;
        }
        __syncthreads();
    }

    // ---- epilogue: x_out = cur @ Wo (16 warps, 8 rows each, 4 batches) ----
    const float4* Wo4 = (const float4*)(wo + (size_t)h * DDIM * DDIM);
    {
        float4 a0 = {0,0,0,0}, a1 = {0,0,0,0}, a2 = {0,0,0,0}, a3 = {0,0,0,0};
        const int d0 = w << 3;
        #pragma unroll 8
        for (int dd = 0; dd < 8; ++dd) {
            int d = d0 + dd;
            float4 wv4 = Wo4[d * 32 + l];
            float4 x4  = *(const float4*)&sm[CURT + d * 4];
            a0.x += x4.x * wv4.x; a0.y += x4.x * wv4.y; a0.z += x4.x * wv4.z; a0.w += x4.x * wv4.w;
            a1.x += x4.y * wv4.x; a1.y += x4.y * wv4.y; a1.z += x4.y * wv4.z; a1.w += x4.y * wv4.w;
            a2.x += x4.z * wv4.x; a2.y += x4.z * wv4.y; a2.z += x4.z * wv4.z; a2.w += x4.z * wv4.w;
            a3.x += x4.w * wv4.x; a3.y += x4.w * wv4.y; a3.z += x4.w * wv4.z; a3.w += x4.w * wv4.w;
        }
        *(float4*)&sm[RED + (w * 4 + 0) * DDIM + (l << 2)] = a0;
        *(float4*)&sm[RED + (w * 4 + 1) * DDIM + (l << 2)] = a1;
        *(float4*)&sm[RED + (w * 4 + 2) * DDIM + (l << 2)] = a2;
        *(float4*)&sm[RED + (w * 4 + 3) * DDIM + (l << 2)] = a3;
    }
    __syncthreads();
    {
        const int b = p4b, e = p4d;
        float v = 0.f;
        #pragma unroll
        for (int ww = 0; ww < 16; ++ww)
            v += sm[RED + (ww * 4 + b) * DDIM + e];
        x_out[(size_t)((b0 + b) * HDIM + h) * DDIM + e] = v;
    }
}

extern "C" void kernel_launch(void* const* d_in, const int* in_sizes, int n_in,
                              void* d_out, int out_size)
{
    const float* x  = (const float*)d_in[0];
    const float* k  = (const float*)d_in[1];
    const float* v  = (const float*)d_in[2];
    const float* wq = (const float*)d_in[3];
    const float* wk = (const float*)d_in[4];
    const float* wv = (const float*)d_in[5];
    const float* wo = (const float*)d_in[6];

    float* out   = (float*)d_out;
    float* k_out = out;
    float* v_out = out + (size_t)BDIM * HDIM * SDIM * DDIM;
    float* x_out = out + (size_t)2 * BDIM * HDIM * SDIM * DDIM;

    fuse_weights_kernel<<<HDIM * 12, 256>>>(wq, wk, wv, wo);

    size_t smem = SMEM_FLOATS * sizeof(float);
    cudaFuncSetAttribute(attn_decode_kernel,
                         cudaFuncAttributeMaxDynamicSharedMemorySize, (int)smem);
    attn_decode_kernel<<<BDIM * HDIM / G, NT, smem>>>(
        x, k, v, wq, wk, wv, wo, k_out, v_out, x_out);
}